// round 5
// baseline (speedup 1.0000x reference)
#include <cuda_runtime.h>
#include <math.h>
#include <stdint.h>

// Problem constants
#define TT   12
#define NN   4096
#define FIN  64
#define HG   128
#define HL   128
#define CC   10
#define EE   65536
#define G4   512   // 4*HL
#define CHUNK   64
#define NCHUNK  (NN / CHUNK)   // 64
#define NW      120            // worker blocks in mega kernel
#define NPH     6              // phase barriers

typedef unsigned long long ull;

#define FMA2(acc, a, b) asm("fma.rn.f32x2 %0, %1, %2, %0;" : "+l"(acc) : "l"(a), "l"(b))
#define ADD2(d, a, b)   asm("add.rn.f32x2 %0, %1, %2;"     : "=l"(d)   : "l"(a), "l"(b))

// ---------------- scratch (static device arrays; no cudaMalloc) ----------------
__device__ float g_hw[(size_t)NN * HG];
__device__ float g_h [(size_t)NN * HG];
__device__ float g_X1[(size_t)NN * G4];
__device__ float g_X2[(size_t)NN * G4];
__device__ float g_h1all[(size_t)NN * HL];
__device__ float g_h2all[(size_t)NN * HL];
__device__ float g_deg[NN];
__device__ float g_dinv[NN];
__device__ int   g_cnt[NN];
__device__ int   g_off[NN + 1];
__device__ int   g_pos[NN];
__device__ int   g_esrc[EE];
__device__ float g_enorm[EE];
__device__ float g_Wih1T[HL * G4], g_Wih2T[HL * G4];
__device__ int   g_prog1, g_prog2;
__device__ int   g_x1ready[NCHUNK];
__device__ int   g_x2ready[NCHUNK];
__device__ int   g_ph_cnt[NPH];
__device__ int   g_ph_flag[NPH];

// ================= launch 0: init / flag reset =================
__global__ void k_init() {
    int i = blockIdx.x * blockDim.x + threadIdx.x;
    if (i < NN) { g_deg[i] = 1.0f; g_cnt[i] = 0; }
    if (i < NCHUNK) { g_x1ready[i] = 0; g_x2ready[i] = 0; }
    if (i < NPH) { g_ph_cnt[i] = 0; g_ph_flag[i] = 0; }
    if (i == 0) { g_prog1 = 0; g_prog2 = 0; }
}

// ================= launch 1: degree accumulation =================
__global__ void k_edge(const int* __restrict__ ei, const float* __restrict__ ew) {
    int e = blockIdx.x * blockDim.x + threadIdx.x;
    if (e < EE) {
        int d = ei[EE + e];
        atomicAdd(&g_deg[d], ew[e]);
        atomicAdd(&g_cnt[d], 1);
    }
}

// ================= launch 2: dinv + prefix scan + CSR fill (1 block) =================
__global__ __launch_bounds__(1024) void k_prep(const int* __restrict__ ei,
                                               const float* __restrict__ ew) {
    __shared__ int s[1024];
    const int tid = threadIdx.x;

    // degree^-1/2
    for (int i = tid; i < NN; i += 1024) {
        float d = g_deg[i];
        g_dinv[i] = d > 0.0f ? rsqrtf(d) : 0.0f;
    }
    __syncthreads();

    // exclusive prefix sum over g_cnt[4096]
    int base = tid * 4;
    int v[4];
    int tot = 0;
#pragma unroll
    for (int i = 0; i < 4; i++) { v[i] = g_cnt[base + i]; tot += v[i]; }
    s[tid] = tot;
    __syncthreads();
    for (int d = 1; d < 1024; d <<= 1) {
        int t2 = (tid >= d) ? s[tid - d] : 0;
        __syncthreads();
        s[tid] += t2;
        __syncthreads();
    }
    int excl = (tid == 0) ? 0 : s[tid - 1];
#pragma unroll
    for (int i = 0; i < 4; i++) {
        g_off[base + i] = excl;
        g_pos[base + i] = excl;
        excl += v[i];
    }
    if (tid == 1023) g_off[NN] = s[1023];
    __syncthreads();

    // CSR fill
    for (int e = tid; e < EE; e += 1024) {
        int src = ei[e];
        int dst = ei[EE + e];
        int p = atomicAdd(&g_pos[dst], 1);
        g_esrc[p] = src;
        g_enorm[p] = g_dinv[src] * ew[e] * g_dinv[dst];
    }
}

// ---------------- fast activations ----------------
__device__ __forceinline__ float sigm_f(float x) {
    return __fdividef(1.0f, 1.0f + __expf(-x));
}
__device__ __forceinline__ float tanh_f(float x) {
    return 1.0f - __fdividef(2.0f, 1.0f + __expf(2.0f * x));
}

// ---------------- worker phase barrier (NW blocks) ----------------
__device__ __forceinline__ void w_barrier(int p) {
    __syncthreads();
    if (threadIdx.x == 0) {
        __threadfence();
        if (atomicAdd(&g_ph_cnt[p], 1) == NW - 1) {
            *(volatile int*)&g_ph_flag[p] = 1;
        } else {
            while (*(volatile int*)&g_ph_flag[p] == 0) __nanosleep(64);
        }
        __threadfence();
    }
    __syncthreads();
}

// ---------------- GCN GEMM: C[4096][128] = A[4096][K] @ W[K][128] ----------------
// 512 threads = 4 sub-tiles of 16 rows x 128 cols.
template <int K>
__device__ void gcn_gemm(int b, const float* __restrict__ A,
                         const float* __restrict__ W, float* __restrict__ C) {
    extern __shared__ ull dyn[];
    float* As = (float*)dyn;                       // [4][16*K]
    const int sub = threadIdx.x >> 7;
    const int c = threadIdx.x & 127;
    float* as = As + sub * 16 * K;
    for (int tg = b; tg < (NN / 16) / 4; tg += NW) {
        size_t row0 = (size_t)(tg * 4 + sub) * 16;
        for (int idx = c; idx < 16 * K; idx += 128)
            as[idx] = __ldcg(&A[row0 * K + idx]);
        __syncthreads();
        float acc[16];
#pragma unroll
        for (int r = 0; r < 16; r++) acc[r] = 0.0f;
#pragma unroll 4
        for (int k4 = 0; k4 < K / 4; k4++) {
            int k = k4 * 4;
            float w0 = W[(size_t)(k + 0) * HG + c];
            float w1 = W[(size_t)(k + 1) * HG + c];
            float w2 = W[(size_t)(k + 2) * HG + c];
            float w3 = W[(size_t)(k + 3) * HG + c];
#pragma unroll
            for (int r = 0; r < 16; r++) {
                float4 a = ((const float4*)(as + r * K))[k4];
                acc[r] += a.x * w0 + a.y * w1 + a.z * w2 + a.w * w3;
            }
        }
#pragma unroll
        for (int r = 0; r < 16; r++)
            C[(row0 + r) * HG + c] = acc[r];
        __syncthreads();
    }
}

// ---------------- GCN gather (CSR) + bias + exact GELU ----------------
__device__ void gcn_gather(int b, const float* __restrict__ hw,
                           const float* __restrict__ bias, float* __restrict__ outp) {
    const int sub = threadIdx.x >> 7;
    const int h = threadIdx.x & 127;
    for (int ng = b; ng < NN / 4; ng += NW) {
        int n = ng * 4 + sub;
        float di = g_dinv[n];
        float acc = __ldcg(&hw[(size_t)n * HG + h]) * di * di;   // self loop
        int e1 = g_off[n + 1];
        for (int e = g_off[n]; e < e1; e++)
            acc += __ldcg(&hw[(size_t)g_esrc[e] * HG + h]) * g_enorm[e];
        float xx = acc + bias[h];
        outp[(size_t)n * HG + h] = 0.5f * xx * (1.0f + erff(xx * 0.70710678118654752f));
    }
}

// ---------------- X GEMM chunk: X[64 rows][512] = A[64][128] @ Wt[128][512] + b ----------------
__device__ void x_gemm_chunk(int ch, const float* __restrict__ A,
                             const float* __restrict__ Wt,
                             const float* __restrict__ ba, const float* __restrict__ bb,
                             float* __restrict__ Cc) {
    extern __shared__ ull dyn[];
    float (*As)[128] = (float (*)[128])dyn;        // 16x128
    const int t = threadIdx.x;                     // 512
    const float binit = ba[t] + bb[t];
    for (int sub = 0; sub < CHUNK / 16; sub++) {
        size_t row0 = (size_t)ch * CHUNK + sub * 16;
        for (int idx = t; idx < 16 * 128; idx += 512)
            As[idx >> 7][idx & 127] = __ldcg(&A[row0 * 128 + idx]);
        __syncthreads();
        float acc[16];
#pragma unroll
        for (int r = 0; r < 16; r++) acc[r] = binit;
#pragma unroll 4
        for (int k4 = 0; k4 < 32; k4++) {
            int k = k4 * 4;
            float w0 = Wt[(size_t)(k + 0) * G4 + t];
            float w1 = Wt[(size_t)(k + 1) * G4 + t];
            float w2 = Wt[(size_t)(k + 2) * G4 + t];
            float w3 = Wt[(size_t)(k + 3) * G4 + t];
#pragma unroll
            for (int r = 0; r < 16; r++) {
                float4 a = ((const float4*)As[r])[k4];
                acc[r] += a.x * w0 + a.y * w1 + a.z * w2 + a.w * w3;
            }
        }
#pragma unroll
        for (int r = 0; r < 16; r++)
            Cc[(row0 + r) * G4 + t] = acc[r];
        __syncthreads();
    }
}

// ---------------- LSTM scan (one persistent block, 512 threads) ----------------
// Thread t owns gate row r = (t&3)*128 + (t>>2).
// Whh row: k=0..87 in registers (44 ull), k=88..127 in smem (10 ulonglong2/thread).
__device__ void scan_body(const float* __restrict__ X,
                          const float* __restrict__ Whh,
                          float* __restrict__ hall,
                          volatile int* ready, volatile int* prog) {
    extern __shared__ ull dyn[];
    float* sh = (float*)dyn;                         // sh[2][HL]
    ulonglong2* sW2 = (ulonglong2*)(dyn + 128);      // sW2[i*512 + t], i=0..9

    const int t = threadIdx.x;
    const int g = t & 3;
    const int u = t >> 2;
    const int r = g * HL + u;

    ull w[44];
    {
        const ull* wrow = (const ull*)(Whh + (size_t)r * HL);
#pragma unroll
        for (int i = 0; i < 44; i++) w[i] = wrow[i];
#pragma unroll
        for (int i = 0; i < 10; i++) {
            ulonglong2 v;
            v.x = wrow[44 + 2 * i];
            v.y = wrow[44 + 2 * i + 1];
            sW2[i * 512 + t] = v;
        }
    }
    if (t < HL) { sh[t] = 0.0f; sh[HL + t] = 0.0f; }
    float c = 0.0f;
    float xv = 0.0f;
    __syncthreads();

    const int lanebase = (t & 31) & ~3;

    for (int n = 0; n < NN; n++) {
        if ((n & (CHUNK - 1)) == 0) {
            if (t == 0) {
                while (ready[n >> 6] == 0) {}
                __threadfence();
            }
            __syncthreads();
            xv = __ldcg(&X[(size_t)n * G4 + r]);
        }

        const ulonglong2* hb2 = (const ulonglong2*)(sh + (n & 1) * HL);

        // prefetch next X within already-flagged chunk
        float xnext = 0.0f;
        if (((n + 1) & (CHUNK - 1)) != 0)
            xnext = __ldcg(&X[(size_t)(n + 1) * G4 + r]);

        ull a0 = 0ull, a1 = 0ull, a2 = 0ull, a3 = 0ull;
#pragma unroll
        for (int i = 0; i < 22; i++) {
            ulonglong2 hv = hb2[i];
            if (i & 1) { FMA2(a2, w[2 * i], hv.x); FMA2(a3, w[2 * i + 1], hv.y); }
            else       { FMA2(a0, w[2 * i], hv.x); FMA2(a1, w[2 * i + 1], hv.y); }
        }
#pragma unroll
        for (int i = 0; i < 10; i++) {
            ulonglong2 wv = sW2[i * 512 + t];
            ulonglong2 hv = hb2[22 + i];
            if (i & 1) { FMA2(a2, wv.x, hv.x); FMA2(a3, wv.y, hv.y); }
            else       { FMA2(a0, wv.x, hv.x); FMA2(a1, wv.y, hv.y); }
        }
        ADD2(a0, a0, a2);
        ADD2(a1, a1, a3);
        ADD2(a0, a0, a1);
        float a_lo, a_hi;
        asm("mov.b64 {%0, %1}, %2;" : "=f"(a_lo), "=f"(a_hi) : "l"(a0));
        float s = a_lo + a_hi + xv;

        float gate = (g == 2) ? tanh_f(s) : sigm_f(s);

        float i_ = __shfl_sync(0xffffffffu, gate, lanebase + 0);
        float f_ = __shfl_sync(0xffffffffu, gate, lanebase + 1);
        float gg = __shfl_sync(0xffffffffu, gate, lanebase + 2);
        float o_ = __shfl_sync(0xffffffffu, gate, lanebase + 3);

        c = f_ * c + i_ * gg;
        float hn = o_ * tanh_f(c);

        if (g == 0) {
            sh[((n + 1) & 1) * HL + u] = hn;
            hall[(size_t)n * HL + u] = hn;
        }
        xv = xnext;
        __syncthreads();

        if ((n & (CHUNK - 1)) == (CHUNK - 1) && t == 0) {
            __threadfence();
            *prog = n + 1;
        }
    }
}

// ---------------- worker role ----------------
__device__ void worker_body(int b, const float* __restrict__ x11,
                            const float* __restrict__ W1, const float* __restrict__ b1,
                            const float* __restrict__ W2, const float* __restrict__ b2,
                            const float* __restrict__ W3, const float* __restrict__ b3,
                            const float* __restrict__ Wih1, const float* __restrict__ bih1,
                            const float* __restrict__ bhh1,
                            const float* __restrict__ Wih2, const float* __restrict__ bih2,
                            const float* __restrict__ bhh2,
                            const float* __restrict__ Wfc, const float* __restrict__ bfc,
                            float* __restrict__ out) {
    const int t = threadIdx.x;

    // P0: Wih transposes + GCN layer-1 GEMM
    for (int i = b * 512 + t; i < G4 * HL; i += NW * 512) {
        int o = i / HL, k = i % HL;
        g_Wih1T[k * G4 + o] = Wih1[i];
        g_Wih2T[k * G4 + o] = Wih2[i];
    }
    gcn_gemm<64>(b, x11, W1, g_hw);
    w_barrier(0);
    gcn_gather(b, g_hw, b1, g_h);
    w_barrier(1);
    gcn_gemm<128>(b, g_h, W2, g_hw);
    w_barrier(2);
    gcn_gather(b, g_hw, b2, g_h);
    w_barrier(3);
    gcn_gemm<128>(b, g_h, W3, g_hw);
    w_barrier(4);
    gcn_gather(b, g_hw, b3, g_h);
    w_barrier(5);

    // P6: X1 chunks (streamed to scan1)
    for (int ch = b; ch < NCHUNK; ch += NW) {
        x_gemm_chunk(ch, g_h, g_Wih1T, bih1, bhh1, g_X1);
        if (t == 0) { __threadfence(); ((volatile int*)g_x1ready)[ch] = 1; }
    }

    // P7: X2 chunks (consume scan1 progress, feed scan2)
    for (int ch = b; ch < NCHUNK; ch += NW) {
        if (t == 0) {
            while (*(volatile int*)&g_prog1 < (ch + 1) * CHUNK) __nanosleep(100);
            __threadfence();
        }
        __syncthreads();
        x_gemm_chunk(ch, g_h1all, g_Wih2T, bih2, bhh2, g_X2);
        if (t == 0) { __threadfence(); ((volatile int*)g_x2ready)[ch] = 1; }
    }

    // P8: FC chunks (consume scan2 progress)
    for (int ch = b; ch < NCHUNK; ch += NW) {
        if (t == 0) {
            while (*(volatile int*)&g_prog2 < (ch + 1) * CHUNK) __nanosleep(200);
            __threadfence();
        }
        __syncthreads();
        for (int idx = t; idx < CHUNK * CC; idx += 512) {
            int n = ch * CHUNK + idx / CC;
            int cls = idx % CC;
            const float4* hv = (const float4*)(g_h2all + (size_t)n * HL);
            const float4* wv = (const float4*)(Wfc + (size_t)cls * HL);
            float s = bfc[cls];
#pragma unroll 8
            for (int k = 0; k < 32; k++) {
                float4 a = __ldcg(&hv[k]);
                float4 ww = wv[k];
                s += a.x * ww.x + a.y * ww.y + a.z * ww.z + a.w * ww.w;
            }
            out[n * CC + cls] = s;
        }
    }
}

// ================= launch 3: mega kernel =================
__global__ __launch_bounds__(512, 1) void k_mega(
    const float* __restrict__ x11,
    const float* __restrict__ W1, const float* __restrict__ b1,
    const float* __restrict__ W2, const float* __restrict__ b2,
    const float* __restrict__ W3, const float* __restrict__ b3,
    const float* __restrict__ Wih1, const float* __restrict__ Whh1,
    const float* __restrict__ bih1, const float* __restrict__ bhh1,
    const float* __restrict__ Wih2, const float* __restrict__ Whh2,
    const float* __restrict__ bih2, const float* __restrict__ bhh2,
    const float* __restrict__ Wfc, const float* __restrict__ bfc,
    float* __restrict__ out) {
    const int role = blockIdx.x;
    if (role == 0) {
        scan_body(g_X1, Whh1, g_h1all, (volatile int*)g_x1ready, (volatile int*)&g_prog1);
    } else if (role == 1) {
        scan_body(g_X2, Whh2, g_h2all, (volatile int*)g_x2ready, (volatile int*)&g_prog2);
    } else {
        worker_body(role - 2, x11, W1, b1, W2, b2, W3, b3,
                    Wih1, bih1, bhh1, Wih2, bih2, bhh2, Wfc, bfc, out);
    }
}

// ---------------- launch ----------------
extern "C" void kernel_launch(void* const* d_in, const int* in_sizes, int n_in,
                              void* d_out, int out_size) {
    const float* x    = (const float*)d_in[0];
    const int*   ei   = (const int*)  d_in[1];
    const float* ew   = (const float*)d_in[2];
    const float* W1   = (const float*)d_in[3];
    const float* b1   = (const float*)d_in[4];
    const float* W2   = (const float*)d_in[5];
    const float* b2   = (const float*)d_in[6];
    const float* W3   = (const float*)d_in[7];
    const float* b3   = (const float*)d_in[8];
    const float* Wih1 = (const float*)d_in[9];
    const float* Whh1 = (const float*)d_in[10];
    const float* bih1 = (const float*)d_in[11];
    const float* bhh1 = (const float*)d_in[12];
    const float* Wih2 = (const float*)d_in[13];
    const float* Whh2 = (const float*)d_in[14];
    const float* bih2 = (const float*)d_in[15];
    const float* bhh2 = (const float*)d_in[16];
    const float* Wfc  = (const float*)d_in[17];
    const float* bfc  = (const float*)d_in[18];
    float* out = (float*)d_out;

    static int smem_set = 0;
    const int MEGA_SMEM = 1024 + 10 * 512 * 16;   // sh[2][128] + sW2 = 82944 B
    if (!smem_set) {
        cudaFuncSetAttribute(k_mega, cudaFuncAttributeMaxDynamicSharedMemorySize, MEGA_SMEM);
        smem_set = 1;
    }

    const float* x11 = x + (size_t)11 * NN * FIN;  // only slice that affects output

    k_init<<<16, 256>>>();
    k_edge<<<EE / 256, 256>>>(ei, ew);
    k_prep<<<1, 1024>>>(ei, ew);
    k_mega<<<NW + 2, 512, MEGA_SMEM>>>(x11, W1, b1, W2, b2, W3, b3,
                                       Wih1, Whh1, bih1, bhh1,
                                       Wih2, Whh2, bih2, bhh2,
                                       Wfc, bfc, out);
}

// round 6
// speedup vs baseline: 1.1913x; 1.1913x over previous
#include <cuda_runtime.h>
#include <math.h>
#include <stdint.h>

// Problem constants
#define TT   12
#define NN   4096
#define FIN  64
#define HG   128
#define HL   128
#define CC   10
#define EE   65536
#define G4   512   // 4*HL
#define CHUNK   64
#define NCHUNK  (NN / CHUNK)   // 64
#define NXW     8              // X2 gemm worker CTAs in fused kernel

typedef unsigned long long ull;

#define FMA2(acc, a, b) asm("fma.rn.f32x2 %0, %1, %2, %0;" : "+l"(acc) : "l"(a), "l"(b))
#define ADD2(d, a, b)   asm("add.rn.f32x2 %0, %1, %2;"     : "=l"(d)   : "l"(a), "l"(b))

// ---------------- scratch (static device arrays; no cudaMalloc) ----------------
__device__ float g_hw[(size_t)NN * HG];
__device__ float g_h [(size_t)NN * HG];
__device__ float g_X1[(size_t)NN * G4];
__device__ float g_X2[(size_t)NN * G4];
__device__ float g_h1all[(size_t)NN * HL];
__device__ float g_h2all[(size_t)NN * HL];
__device__ float g_deg[NN];
__device__ float g_dinv[NN];
__device__ int   g_cnt[NN];
__device__ int   g_off[NN + 1];
__device__ int   g_pos[NN];
__device__ int   g_esrc[EE];
__device__ float g_enorm[EE];
__device__ float g_Wih1T[HL * G4], g_Wih2T[HL * G4];
__device__ int   g_prog1[2];          // per-rank scan1 progress
__device__ int   g_x2ready[NCHUNK];

// ---------------- PTX helpers ----------------
__device__ __forceinline__ uint32_t smem_u32(const void* p) {
    uint32_t a;
    asm("{ .reg .u64 t; cvta.to.shared.u64 t, %1; cvt.u32.u64 %0, t; }" : "=r"(a) : "l"(p));
    return a;
}
__device__ __forceinline__ uint32_t my_cluster_rank() {
    uint32_t r;
    asm("mov.u32 %0, %%cluster_ctarank;" : "=r"(r));
    return r;
}
__device__ __forceinline__ void cluster_sync_all() {
    asm volatile("barrier.cluster.arrive.aligned;" ::: "memory");
    asm volatile("barrier.cluster.wait.aligned;" ::: "memory");
}
__device__ __forceinline__ void mbar_init(uint32_t a, uint32_t cnt) {
    asm volatile("mbarrier.init.shared.b64 [%0], %1;" :: "r"(a), "r"(cnt) : "memory");
}
__device__ __forceinline__ void dsmem_store_f32(uint32_t laddr, uint32_t peer, float v) {
    asm volatile("{ .reg .b32 ra; mapa.shared::cluster.u32 ra, %0, %1; "
                 "st.shared::cluster.b32 [ra], %2; }"
                 :: "r"(laddr), "r"(peer), "r"(__float_as_uint(v)) : "memory");
}
__device__ __forceinline__ void mbar_arrive_peer_release(uint32_t laddr, uint32_t peer) {
    asm volatile("{ .reg .b32 ra; mapa.shared::cluster.u32 ra, %0, %1; "
                 "mbarrier.arrive.release.cluster.shared::cluster.b64 _, [ra]; }"
                 :: "r"(laddr), "r"(peer) : "memory");
}
__device__ __forceinline__ void mbar_wait_parity(uint32_t a, uint32_t parity) {
    uint32_t done;
    asm volatile("{ .reg .pred p; "
                 "mbarrier.try_wait.parity.acquire.cluster.shared::cta.b64 p, [%1], %2; "
                 "selp.b32 %0, 1, 0, p; }"
                 : "=r"(done) : "r"(a), "r"(parity) : "memory");
    while (!done) {
        asm volatile("{ .reg .pred p; "
                     "mbarrier.try_wait.parity.acquire.cluster.shared::cta.b64 p, [%1], %2, 0x989680; "
                     "selp.b32 %0, 1, 0, p; }"
                     : "=r"(done) : "r"(a), "r"(parity) : "memory");
    }
}

// ================= launch 0: init / flag reset =================
__global__ void k_init() {
    int i = blockIdx.x * blockDim.x + threadIdx.x;
    if (i < NN) { g_deg[i] = 1.0f; g_cnt[i] = 0; }
    if (i < NCHUNK) g_x2ready[i] = 0;
    if (i < 2) g_prog1[i] = 0;
}

// ================= launch 1: degree accumulation =================
__global__ void k_edge(const int* __restrict__ ei, const float* __restrict__ ew) {
    int e = blockIdx.x * blockDim.x + threadIdx.x;
    if (e < EE) {
        int d = ei[EE + e];
        atomicAdd(&g_deg[d], ew[e]);
        atomicAdd(&g_cnt[d], 1);
    }
}

// ================= launch 2: dinv + prefix scan + CSR fill (1 block) =================
__global__ __launch_bounds__(1024) void k_prep(const int* __restrict__ ei,
                                               const float* __restrict__ ew) {
    __shared__ int s[1024];
    const int tid = threadIdx.x;

    for (int i = tid; i < NN; i += 1024) {
        float d = g_deg[i];
        g_dinv[i] = d > 0.0f ? rsqrtf(d) : 0.0f;
    }
    __syncthreads();

    int base = tid * 4;
    int v[4];
    int tot = 0;
#pragma unroll
    for (int i = 0; i < 4; i++) { v[i] = g_cnt[base + i]; tot += v[i]; }
    s[tid] = tot;
    __syncthreads();
    for (int d = 1; d < 1024; d <<= 1) {
        int t2 = (tid >= d) ? s[tid - d] : 0;
        __syncthreads();
        s[tid] += t2;
        __syncthreads();
    }
    int excl = (tid == 0) ? 0 : s[tid - 1];
#pragma unroll
    for (int i = 0; i < 4; i++) {
        g_off[base + i] = excl;
        g_pos[base + i] = excl;
        excl += v[i];
    }
    if (tid == 1023) g_off[NN] = s[1023];
    __syncthreads();

    for (int e = tid; e < EE; e += 1024) {
        int src = ei[e];
        int dst = ei[EE + e];
        int p = atomicAdd(&g_pos[dst], 1);
        g_esrc[p] = src;
        g_enorm[p] = g_dinv[src] * ew[e] * g_dinv[dst];
    }
}

// ---------------- weight transpose:  W[OC][K] -> Wt[K][OC] ----------------
__global__ void k_tr(const float* __restrict__ W, float* __restrict__ Wt, int OC, int K) {
    int i = blockIdx.x * blockDim.x + threadIdx.x;
    if (i < OC * K) {
        int o = i / K, k = i % K;
        Wt[k * OC + o] = W[i];
    }
}

// ---------------- GEMM:  C[M][OC] = A[M][K] @ Wt   (Wt stored [K][OC]) ----------------
template <int K, int OC, int ROWS, bool BIAS2>
__global__ void k_gemm_kn(const float* __restrict__ A, const float* __restrict__ Wt,
                          const float* __restrict__ ba, const float* __restrict__ bb,
                          float* __restrict__ Cc) {
    __shared__ float As[ROWS][K];
    const int c = threadIdx.x;
    const size_t row0 = (size_t)blockIdx.x * ROWS;
    for (int idx = c; idx < ROWS * K; idx += OC)
        As[idx / K][idx % K] = A[row0 * K + idx];
    __syncthreads();

    float binit = 0.0f;
    if constexpr (BIAS2) binit = ba[c] + bb[c];
    float acc[ROWS];
#pragma unroll
    for (int r = 0; r < ROWS; r++) acc[r] = binit;

#pragma unroll 4
    for (int k4 = 0; k4 < K / 4; k4++) {
        int k = k4 * 4;
        float w0 = Wt[(size_t)(k + 0) * OC + c];
        float w1 = Wt[(size_t)(k + 1) * OC + c];
        float w2 = Wt[(size_t)(k + 2) * OC + c];
        float w3 = Wt[(size_t)(k + 3) * OC + c];
#pragma unroll
        for (int r = 0; r < ROWS; r++) {
            float4 a = ((const float4*)As[r])[k4];
            acc[r] += a.x * w0 + a.y * w1 + a.z * w2 + a.w * w3;
        }
    }
#pragma unroll
    for (int r = 0; r < ROWS; r++)
        Cc[(row0 + r) * OC + c] = acc[r];
}

// ---------------- GCN aggregation (CSR gather) + bias + exact GELU ----------------
__global__ void k_gather(const float* __restrict__ hw, const float* __restrict__ b,
                         float* __restrict__ out) {
    const int n = blockIdx.x;
    const int h = threadIdx.x;
    float di = g_dinv[n];
    float acc = hw[n * HG + h] * di * di;
    int e0 = g_off[n], e1 = g_off[n + 1];
    for (int e = e0; e < e1; e++)
        acc += hw[g_esrc[e] * HG + h] * g_enorm[e];
    float x = acc + b[h];
    out[(size_t)n * HG + h] = 0.5f * x * (1.0f + erff(x * 0.70710678118654752f));
}

// ---------------- fast activations ----------------
__device__ __forceinline__ float sigm_f(float x) {
    return __fdividef(1.0f, 1.0f + __expf(-x));
}
__device__ __forceinline__ float tanh_f(float x) {
    return 1.0f - __fdividef(2.0f, 1.0f + __expf(2.0f * x));
}

// ---------------- LSTM scan: 2-CTA cluster, 256 threads/CTA ----------------
// CTA rank owns h-outputs u_global = rank*64 + (t>>2); thread t owns gate row
// r = (t&3)*128 + rank*64 + (t>>2) with ALL 128 weights in registers.
// Per step: dot via packed f32x2 FMA over broadcast-smem h; gate exchange via
// quad shfl; 64 h values stored locally + DSMEM to peer; per-step mbarrier
// handshake (remote release-arrive + local acquire parity wait).
__device__ void scan_cluster(const float* __restrict__ X,
                             const float* __restrict__ Whh,
                             float* __restrict__ hall,
                             volatile int* ready,     // null for scan1
                             volatile int* prog,      // per-rank slot, null for scan2
                             float* s_h, ull* s_mbar) {
    const int t = threadIdx.x;
    const int g = t & 3;
    const int u = t >> 2;                 // 0..63
    const int rank = (int)my_cluster_rank();
    const int peer = rank ^ 1;
    const int r = g * HL + rank * 64 + u; // gate row
    const uint32_t mbar_addr = smem_u32(s_mbar);
    const uint32_t sh_addr = smem_u32(s_h);

    ull w[64];
    {
        const ull* wrow = (const ull*)(Whh + (size_t)r * HL);
#pragma unroll
        for (int i = 0; i < 64; i++) w[i] = wrow[i];
    }
    s_h[t] = 0.0f;                        // 256 threads zero both 128-buffers
    if (t == 0) mbar_init(mbar_addr, 1);
    __syncthreads();
    cluster_sync_all();                   // peer mbarrier init + zeros visible

    float c = 0.0f;
    float xv = 0.0f;
    const int lanebase = (t & 31) & ~3;

    for (int n = 0; n < NN; n++) {
        if ((n & (CHUNK - 1)) == 0) {
            if (t == 0 && ready) {
                while (ready[n >> 6] == 0) __nanosleep(60);
                __threadfence();
            }
            __syncthreads();
            xv = __ldcg(&X[(size_t)n * G4 + r]);
        }

        const ulonglong2* hb2 = (const ulonglong2*)(s_h + (n & 1) * HL);

        float xnext = 0.0f;
        if (((n + 1) & (CHUNK - 1)) != 0)
            xnext = __ldcg(&X[(size_t)(n + 1) * G4 + r]);

        ull a0 = 0ull, a1 = 0ull, a2 = 0ull, a3 = 0ull;
#pragma unroll
        for (int i = 0; i < 32; i++) {
            ulonglong2 hv = hb2[i];
            if (i & 1) { FMA2(a2, w[2 * i], hv.x); FMA2(a3, w[2 * i + 1], hv.y); }
            else       { FMA2(a0, w[2 * i], hv.x); FMA2(a1, w[2 * i + 1], hv.y); }
        }
        ADD2(a0, a0, a2);
        ADD2(a1, a1, a3);
        ADD2(a0, a0, a1);
        float a_lo, a_hi;
        asm("mov.b64 {%0, %1}, %2;" : "=f"(a_lo), "=f"(a_hi) : "l"(a0));
        float s = a_lo + a_hi + xv;

        float gate = (g == 2) ? tanh_f(s) : sigm_f(s);

        float i_ = __shfl_sync(0xffffffffu, gate, lanebase + 0);
        float f_ = __shfl_sync(0xffffffffu, gate, lanebase + 1);
        float gg = __shfl_sync(0xffffffffu, gate, lanebase + 2);
        float o_ = __shfl_sync(0xffffffffu, gate, lanebase + 3);

        c = f_ * c + i_ * gg;
        float hn = o_ * tanh_f(c);

        if (g == 0) {
            int slot = ((n + 1) & 1) * HL + rank * 64 + u;
            s_h[slot] = hn;
            dsmem_store_f32(sh_addr + slot * 4, peer, hn);
            hall[(size_t)n * HL + rank * 64 + u] = hn;
        }
        __syncthreads();
        if (t == 0) {
            mbar_arrive_peer_release(mbar_addr, peer);
            if (prog && (n & (CHUNK - 1)) == (CHUNK - 1)) {
                __threadfence();
                *prog = n + 1;
            }
        }
        mbar_wait_parity(mbar_addr, n & 1);
        xv = xnext;
    }
}

// ---------------- X2 GEMM worker (256 threads, 2 cols/thread) ----------------
__device__ void x2_worker(int b, const float* __restrict__ h1all,
                          const float* __restrict__ Wt,
                          const float* __restrict__ ba, const float* __restrict__ bb,
                          float* __restrict__ X2, float* s_As /*16*128*/) {
    const int t = threadIdx.x;            // 0..255
    const int c0 = t, c1 = t + 256;
    const float bi0 = ba[c0] + bb[c0];
    const float bi1 = ba[c1] + bb[c1];

    for (int ch = b; ch < NCHUNK; ch += NXW) {
        if (t == 0) {
            int target = (ch + 1) * CHUNK;
            for (;;) {
                int p0 = *(volatile int*)&g_prog1[0];
                int p1 = *(volatile int*)&g_prog1[1];
                if (p0 >= target && p1 >= target) break;
                __nanosleep(100);
            }
            __threadfence();
        }
        __syncthreads();

        for (int sub = 0; sub < CHUNK / 16; sub++) {
            size_t row0 = (size_t)ch * CHUNK + sub * 16;
            for (int idx = t; idx < 16 * 128; idx += 256)
                s_As[idx] = __ldcg(&h1all[row0 * 128 + idx]);
            __syncthreads();

            float acc0[16], acc1[16];
#pragma unroll
            for (int r = 0; r < 16; r++) { acc0[r] = bi0; acc1[r] = bi1; }
#pragma unroll 4
            for (int k4 = 0; k4 < 32; k4++) {
                int k = k4 * 4;
                float w00 = Wt[(size_t)(k + 0) * G4 + c0];
                float w01 = Wt[(size_t)(k + 1) * G4 + c0];
                float w02 = Wt[(size_t)(k + 2) * G4 + c0];
                float w03 = Wt[(size_t)(k + 3) * G4 + c0];
                float w10 = Wt[(size_t)(k + 0) * G4 + c1];
                float w11 = Wt[(size_t)(k + 1) * G4 + c1];
                float w12 = Wt[(size_t)(k + 2) * G4 + c1];
                float w13 = Wt[(size_t)(k + 3) * G4 + c1];
#pragma unroll
                for (int r = 0; r < 16; r++) {
                    float4 a = ((const float4*)(s_As + r * 128))[k4];
                    acc0[r] += a.x * w00 + a.y * w01 + a.z * w02 + a.w * w03;
                    acc1[r] += a.x * w10 + a.y * w11 + a.z * w12 + a.w * w13;
                }
            }
#pragma unroll
            for (int r = 0; r < 16; r++) {
                X2[(row0 + r) * G4 + c0] = acc0[r];
                X2[(row0 + r) * G4 + c1] = acc1[r];
            }
            __syncthreads();
        }
        if (t == 0) {
            __threadfence();
            ((volatile int*)g_x2ready)[ch] = 1;
        }
    }
}

// ================= fused kernel: scan1 cluster | scan2 cluster | X2 workers =================
__global__ __launch_bounds__(256, 1) __cluster_dims__(2, 1, 1)
void k_fused(const float* __restrict__ Whh1, const float* __restrict__ Whh2,
             const float* __restrict__ bih2, const float* __restrict__ bhh2) {
    __shared__ __align__(16) float s_h[2 * HL];
    __shared__ ull s_mbar;
    __shared__ __align__(16) float s_As[16 * 128];

    const int blk = blockIdx.x;
    if (blk < 2) {
        scan_cluster(g_X1, Whh1, g_h1all, nullptr,
                     (volatile int*)&g_prog1[blk & 1], s_h, &s_mbar);
    } else if (blk < 4) {
        scan_cluster(g_X2, Whh2, g_h2all, (volatile int*)g_x2ready,
                     nullptr, s_h, &s_mbar);
    } else {
        cluster_sync_all();   // keep worker cluster pairs consistent (no-op use)
        x2_worker(blk - 4, g_h1all, g_Wih2T, bih2, bhh2, g_X2, s_As);
    }
}

// ---------------- final FC: out[n][c] = h2all[n] . Wfc[c] + bfc[c] ----------------
__global__ void k_fc(const float* __restrict__ h2all, const float* __restrict__ Wfc,
                     const float* __restrict__ bfc, float* __restrict__ out) {
    const int n = blockIdx.x;
    const int lane = threadIdx.x;
    float4 hv = ((const float4*)(h2all + (size_t)n * HL))[lane];
#pragma unroll
    for (int c = 0; c < CC; c++) {
        float4 w = ((const float4*)(Wfc + (size_t)c * HL))[lane];
        float p = hv.x * w.x + hv.y * w.y + hv.z * w.z + hv.w * w.w;
#pragma unroll
        for (int s = 16; s; s >>= 1) p += __shfl_xor_sync(0xffffffffu, p, s);
        if (lane == 0) out[n * CC + c] = p + bfc[c];
    }
}

// ---------------- launch ----------------
extern "C" void kernel_launch(void* const* d_in, const int* in_sizes, int n_in,
                              void* d_out, int out_size) {
    const float* x    = (const float*)d_in[0];
    const int*   ei   = (const int*)  d_in[1];
    const float* ew   = (const float*)d_in[2];
    const float* W1   = (const float*)d_in[3];
    const float* b1   = (const float*)d_in[4];
    const float* W2   = (const float*)d_in[5];
    const float* b2   = (const float*)d_in[6];
    const float* W3   = (const float*)d_in[7];
    const float* b3   = (const float*)d_in[8];
    const float* Wih1 = (const float*)d_in[9];
    const float* Whh1 = (const float*)d_in[10];
    const float* bih1 = (const float*)d_in[11];
    const float* bhh1 = (const float*)d_in[12];
    const float* Wih2 = (const float*)d_in[13];
    const float* Whh2 = (const float*)d_in[14];
    const float* bih2 = (const float*)d_in[15];
    const float* bhh2 = (const float*)d_in[16];
    const float* Wfc  = (const float*)d_in[17];
    const float* bfc  = (const float*)d_in[18];
    float* out = (float*)d_out;

    float *d_hw, *d_h, *d_X1, *d_h1all, *d_h2all, *d_Wih1T, *d_Wih2T;
    cudaGetSymbolAddress((void**)&d_hw,    g_hw);
    cudaGetSymbolAddress((void**)&d_h,     g_h);
    cudaGetSymbolAddress((void**)&d_X1,    g_X1);
    cudaGetSymbolAddress((void**)&d_h1all, g_h1all);
    cudaGetSymbolAddress((void**)&d_h2all, g_h2all);
    cudaGetSymbolAddress((void**)&d_Wih1T, g_Wih1T);
    cudaGetSymbolAddress((void**)&d_Wih2T, g_Wih2T);

    const float* x11 = x + (size_t)11 * NN * FIN;  // only slice that affects output

    // preprocessing
    k_init<<<16, 256>>>();
    k_edge<<<EE / 256, 256>>>(ei, ew);
    k_prep<<<1, 1024>>>(ei, ew);

    // Wih transposes to [K][OC]
    int trB = (HL * G4 + 255) / 256;
    k_tr<<<trB, 256>>>(Wih1, d_Wih1T, G4, HL);
    k_tr<<<trB, 256>>>(Wih2, d_Wih2T, G4, HL);

    // GCN x3 (t=11 slice)
    k_gemm_kn<64, 128, 16, false><<<NN / 16, 128>>>(x11, W1, nullptr, nullptr, d_hw);
    k_gather<<<NN, 128>>>(d_hw, b1, d_h);
    k_gemm_kn<128, 128, 16, false><<<NN / 16, 128>>>(d_h, W2, nullptr, nullptr, d_hw);
    k_gather<<<NN, 128>>>(d_hw, b2, d_h);
    k_gemm_kn<128, 128, 16, false><<<NN / 16, 128>>>(d_h, W3, nullptr, nullptr, d_hw);
    k_gather<<<NN, 128>>>(d_hw, b3, d_h);

    // X1 = h @ Wih1^T + (bih1 + bhh1)
    k_gemm_kn<128, 512, 16, true><<<NN / 16, 512>>>(d_h, d_Wih1T, bih1, bhh1, d_X1);

    // fused pipelined: scan1 (2-CTA cluster) || X2 GEMM workers || scan2 (2-CTA cluster)
    k_fused<<<4 + NXW, 256>>>(Whh1, Whh2, bih2, bhh2);

    // final FC
    k_fc<<<NN, 32>>>(d_h2all, Wfc, bfc, out);
}